// round 13
// baseline (speedup 1.0000x reference)
#include <cuda_runtime.h>
#include <cuda_bf16.h>
#include <cstdint>

#define NTOK 65
#define MTOK 129
#define NHEAD 16
#define HDIM 64
#define CDIM 1024

// fp32 intermediates
__device__ float g_q [512 * NTOK * CDIM];
__device__ float g_kv[512 * MTOK * 2 * CDIM];
__device__ float g_ao[512 * NTOK * CDIM];     // tf32-rounded + k-permuted (attention)
// tf32-rounded, k-permuted weights [N][perm(K)]
__device__ float g_wqt [CDIM * CDIM];
__device__ float g_wkvt[2 * CDIM * CDIM];
__device__ float g_wpt [CDIM * CDIM];

__device__ __forceinline__ unsigned f2tf32(float x) {
    unsigned r;
    asm("cvt.rna.tf32.f32 %0, %1;" : "=r"(r) : "f"(x));
    return r;
}
__device__ __forceinline__ void cp16s(uint32_t s, const float* g) {
    asm volatile("cp.async.cg.shared.global [%0], [%1], 16;"
                 :: "r"(s), "l"(g) : "memory");
}
__device__ __forceinline__ uint32_t smem_u32(const void* p) {
    uint32_t a;
    asm("{ .reg .u64 t; cvta.to.shared.u64 t, %1; cvt.u32.u64 %0, t; }"
        : "=r"(a) : "l"(p));
    return a;
}
#define MMA_TF32(acc, a0, a1, a2, a3, b0, b1) \
    asm volatile( \
        "mma.sync.aligned.m16n8k8.row.col.f32.tf32.tf32.f32 " \
        "{%0,%1,%2,%3}, {%4,%5,%6,%7}, {%8,%9}, {%0,%1,%2,%3};" \
        : "+f"((acc)[0]), "+f"((acc)[1]), "+f"((acc)[2]), "+f"((acc)[3]) \
        : "r"(a0), "r"(a1), "r"(a2), "r"(a3), "r"(b0), "r"(b1))

// ---------------------------------------------------------------------------
// W[K][N] fp32 -> Wt[N][perm(K)] tf32-rounded; p(k)=(k&~7)|((k&3)<<1)|((k>>2)&1)
// ---------------------------------------------------------------------------
__global__ __launch_bounds__(256) void transpose_tf32_perm(
    const float* __restrict__ W, float* __restrict__ Wt, int K, int N)
{
    __shared__ float t[32][33];
    const int n0 = blockIdx.x * 32, k0 = blockIdx.y * 32;
    const int tx = threadIdx.x & 31, ty = threadIdx.x >> 5;
    #pragma unroll
    for (int i = 0; i < 4; i++)
        t[ty + 8 * i][tx] = W[(size_t)(k0 + ty + 8 * i) * N + n0 + tx];
    __syncthreads();
    const int pk = (tx & ~7) | ((tx & 3) << 1) | ((tx >> 2) & 1);
    #pragma unroll
    for (int i = 0; i < 4; i++)
        Wt[(size_t)(n0 + ty + 8 * i) * K + k0 + pk] =
            __uint_as_float(f2tf32(t[tx][ty + 8 * i]));
}

// ---------------------------------------------------------------------------
// GEMM variant 1 (raw A): C = A_raw[M,K] @ Bt[N,perm(K)]^T + bias
// A: raw fp32, stride 36, scalar LDS + cvt.rna in-register.
// B: pre-rounded/permuted, stride 40, LDS.64.
// 128x128x32 tile, 8 warps 64x32, single-sync double buffer, 2 CTA/SM.
// ---------------------------------------------------------------------------
#define AGS 36
#define BGS 40
#define A_WORDS (128 * AGS)
#define STAGE_W (A_WORDS + 128 * BGS)   // 9728 words

__global__ __launch_bounds__(256, 2) void gemm_raw(
    const float* __restrict__ A, const float* __restrict__ Bt,
    const float* __restrict__ bias, float* __restrict__ C,
    int M, int N, int K)
{
    extern __shared__ float smg[];

    const int tid  = threadIdx.x;
    const int lane = tid & 31;
    const int warp = tid >> 5;
    const int wm   = warp >> 2;
    const int wn   = warp & 3;
    const int g    = lane >> 2;
    const int t    = lane & 3;

    const int bn = blockIdx.x, bm = blockIdx.y;
    const float* Ag = A  + (size_t)bm * 128 * K;
    const float* Bg = Bt + (size_t)bn * 128 * K;
    const uint32_t sb = smem_u32(smg);

    float acc[4][4][4];
    #pragma unroll
    for (int i = 0; i < 4; i++)
        #pragma unroll
        for (int j = 0; j < 4; j++)
            #pragma unroll
            for (int r = 0; r < 4; r++) acc[i][j][r] = 0.f;

    auto issue = [&](int kt, int s) {
        const uint32_t base = sb + s * (STAGE_W * 4);
        #pragma unroll
        for (int it = 0; it < 8; it++) {
            int idx = tid + it * 256;
            int row = (idx >> 3) & 127, c = idx & 7;
            if (idx < 1024)
                cp16s(base + (row * AGS + c * 4) * 4,
                      Ag + (size_t)row * K + kt + c * 4);
            else
                cp16s(base + (A_WORDS + row * BGS + c * 4) * 4,
                      Bg + (size_t)row * K + kt + c * 4);
        }
        asm volatile("cp.async.commit_group;" ::: "memory");
    };

    issue(0, 0);
    const int NT = K >> 5;
    for (int ti = 0; ti < NT; ti++) {
        const int cur = ti & 1;
        asm volatile("cp.async.wait_group 0;" ::: "memory");
        __syncthreads();
        if (ti + 1 < NT) issue((ti + 1) << 5, cur ^ 1);

        const float* As = smg + cur * STAGE_W;
        const float* Bs = As + A_WORDS;
        #pragma unroll
        for (int ks = 0; ks < 4; ks++) {
            const int kb = ks * 8;
            unsigned af[4][4];
            #pragma unroll
            for (int i = 0; i < 4; i++) {
                int r = wm * 64 + i * 16 + g;
                af[i][0] = f2tf32(As[r * AGS + kb + t]);
                af[i][1] = f2tf32(As[(r + 8) * AGS + kb + t]);
                af[i][2] = f2tf32(As[r * AGS + kb + t + 4]);
                af[i][3] = f2tf32(As[(r + 8) * AGS + kb + t + 4]);
            }
            unsigned bf[4][2];
            #pragma unroll
            for (int j = 0; j < 4; j++) {
                int n = wn * 32 + j * 8 + g;
                uint2 bb = *(const uint2*)(Bs + n * BGS + kb + 2 * t);
                bf[j][0] = bb.x; bf[j][1] = bb.y;
            }
            #pragma unroll
            for (int i = 0; i < 4; i++)
                #pragma unroll
                for (int j = 0; j < 4; j++)
                    MMA_TF32(acc[i][j], af[i][0], af[i][1], af[i][2], af[i][3],
                             bf[j][0], bf[j][1]);
        }
    }

    #pragma unroll
    for (int i = 0; i < 4; i++) {
        int row0 = bm * 128 + wm * 64 + i * 16 + g;
        #pragma unroll
        for (int j = 0; j < 4; j++) {
            int col = bn * 128 + wn * 32 + j * 8 + t * 2;
            float b0 = bias[col], b1 = bias[col + 1];
            float2 v0 = make_float2(acc[i][j][0] + b0, acc[i][j][1] + b1);
            float2 v1 = make_float2(acc[i][j][2] + b0, acc[i][j][3] + b1);
            *(float2*)(C + (size_t)row0 * N + col)       = v0;
            *(float2*)(C + (size_t)(row0 + 8) * N + col) = v1;
        }
    }
}

// ---------------------------------------------------------------------------
// GEMM variant 2 (pre-permuted A): A already tf32-rounded + k-permuted.
// Both operands stride 40, LDS.64 fragments, zero cvt in the hot loop.
// ---------------------------------------------------------------------------
#define PSTAGE_W (2 * 128 * BGS)        // 10240 words

__global__ __launch_bounds__(256, 2) void gemm_pp(
    const float* __restrict__ A, const float* __restrict__ Bt,
    const float* __restrict__ bias, float* __restrict__ C,
    int M, int N, int K)
{
    extern __shared__ float smg[];

    const int tid  = threadIdx.x;
    const int lane = tid & 31;
    const int warp = tid >> 5;
    const int wm   = warp >> 2;
    const int wn   = warp & 3;
    const int g    = lane >> 2;
    const int t    = lane & 3;

    const int bn = blockIdx.x, bm = blockIdx.y;
    const float* Ag = A  + (size_t)bm * 128 * K;
    const float* Bg = Bt + (size_t)bn * 128 * K;
    const uint32_t sb = smem_u32(smg);

    float acc[4][4][4];
    #pragma unroll
    for (int i = 0; i < 4; i++)
        #pragma unroll
        for (int j = 0; j < 4; j++)
            #pragma unroll
            for (int r = 0; r < 4; r++) acc[i][j][r] = 0.f;

    auto issue = [&](int kt, int s) {
        const uint32_t base = sb + s * (PSTAGE_W * 4);
        #pragma unroll
        for (int it = 0; it < 8; it++) {
            int idx = tid + it * 256;
            int row = (idx >> 3) & 127, c = idx & 7;
            if (idx < 1024)
                cp16s(base + (row * BGS + c * 4) * 4,
                      Ag + (size_t)row * K + kt + c * 4);
            else
                cp16s(base + ((128 * BGS) + row * BGS + c * 4) * 4,
                      Bg + (size_t)row * K + kt + c * 4);
        }
        asm volatile("cp.async.commit_group;" ::: "memory");
    };

    issue(0, 0);
    const int NT = K >> 5;
    for (int ti = 0; ti < NT; ti++) {
        const int cur = ti & 1;
        asm volatile("cp.async.wait_group 0;" ::: "memory");
        __syncthreads();
        if (ti + 1 < NT) issue((ti + 1) << 5, cur ^ 1);

        const float* As = smg + cur * PSTAGE_W;
        const float* Bs = As + 128 * BGS;
        #pragma unroll
        for (int ks = 0; ks < 4; ks++) {
            const int k0 = ks * 8 + 2 * t;
            unsigned af[4][4];
            #pragma unroll
            for (int i = 0; i < 4; i++) {
                int r = wm * 64 + i * 16 + g;
                uint2 lo = *(const uint2*)(As + r * BGS + k0);
                uint2 hi = *(const uint2*)(As + (r + 8) * BGS + k0);
                af[i][0] = lo.x; af[i][2] = lo.y;
                af[i][1] = hi.x; af[i][3] = hi.y;
            }
            unsigned bf[4][2];
            #pragma unroll
            for (int j = 0; j < 4; j++) {
                int n = wn * 32 + j * 8 + g;
                uint2 bb = *(const uint2*)(Bs + n * BGS + k0);
                bf[j][0] = bb.x; bf[j][1] = bb.y;
            }
            #pragma unroll
            for (int i = 0; i < 4; i++)
                #pragma unroll
                for (int j = 0; j < 4; j++)
                    MMA_TF32(acc[i][j], af[i][0], af[i][1], af[i][2], af[i][3],
                             bf[j][0], bf[j][1]);
        }
    }

    #pragma unroll
    for (int i = 0; i < 4; i++) {
        int row0 = bm * 128 + wm * 64 + i * 16 + g;
        #pragma unroll
        for (int j = 0; j < 4; j++) {
            int col = bn * 128 + wn * 32 + j * 8 + t * 2;
            float b0 = bias[col], b1 = bias[col + 1];
            float2 v0 = make_float2(acc[i][j][0] + b0, acc[i][j][1] + b1);
            float2 v1 = make_float2(acc[i][j][2] + b0, acc[i][j][3] + b1);
            *(float2*)(C + (size_t)row0 * N + col)       = v0;
            *(float2*)(C + (size_t)(row0 + 8) * N + col) = v1;
        }
    }
}

// ---------------------------------------------------------------------------
// Tensor-core attention (R11 core; output rounded + k-permuted for gemm_pp)
// ---------------------------------------------------------------------------
#define SSTR 136
#define QKS 72
#define OFF_Q (80 * SSTR)
#define OFF_K (OFF_Q + 80 * QKS)
#define OFF_TB (OFF_K + 129 * QKS)
#define ATTN_W (OFF_TB + 392)

__global__ __launch_bounds__(256, 2) void attn_tc(
    const float* __restrict__ q, const float* __restrict__ kv,
    const int* __restrict__ mask_l,
    const int* __restrict__ mask_r,
    const int* __restrict__ nW_ptr,
    const float* __restrict__ rel_table,
    const float* __restrict__ cls_self,
    const float* __restrict__ cls_up,
    const float* __restrict__ cls_down,
    float* __restrict__ ao)
{
    const int h = blockIdx.x;
    const int b = blockIdx.y;
    const int tid = threadIdx.x;
    const int lane = tid & 31;
    const int warp = tid >> 5;
    const int g = lane >> 2;
    const int t = lane & 3;

    extern __shared__ float sm[];
    float* Ss = sm;
    float* Qs = sm + OFF_Q;
    float* Ks = sm + OFF_K;
    float* Vs = sm + OFF_Q;               // overlay (after QK)
    float* tb = sm + OFF_TB;

    for (int i = tid; i < 191; i += 256) tb[i] = rel_table[i * NHEAD + h];
    if (tid == 0) tb[191] = cls_self[h];
    for (int i = tid; i < 128; i += 256) tb[192 + i] = cls_up[h * (MTOK - 1) + i];
    for (int i = tid; i < 64; i += 256) tb[320 + i] = cls_down[h * (NTOK - 1) + i];

    const float* qb = q + (size_t)b * NTOK * CDIM + h * HDIM;
    for (int idx = tid; idx < 65 * 8; idx += 256) {
        int r = idx >> 3, gp = idx & 7;
        const float* p = qb + (size_t)r * CDIM + gp * 8;
        float4 a = *(const float4*)p, c = *(const float4*)(p + 4);
        uint4 w0, w1;
        w0.x = f2tf32(a.x); w0.y = f2tf32(c.x); w0.z = f2tf32(a.y); w0.w = f2tf32(c.y);
        w1.x = f2tf32(a.z); w1.y = f2tf32(c.z); w1.z = f2tf32(a.w); w1.w = f2tf32(c.w);
        *(uint4*)(Qs + r * QKS + gp * 8)     = w0;
        *(uint4*)(Qs + r * QKS + gp * 8 + 4) = w1;
    }
    const float* kb = kv + (size_t)b * MTOK * 2 * CDIM + h * HDIM;
    for (int idx = tid; idx < 129 * 8; idx += 256) {
        int r = idx >> 3, gp = idx & 7;
        const float* p = kb + (size_t)r * 2048 + gp * 8;
        float4 a = *(const float4*)p, c = *(const float4*)(p + 4);
        uint4 w0, w1;
        w0.x = f2tf32(a.x); w0.y = f2tf32(c.x); w0.z = f2tf32(a.y); w0.w = f2tf32(c.y);
        w1.x = f2tf32(a.z); w1.y = f2tf32(c.z); w1.z = f2tf32(a.w); w1.w = f2tf32(c.w);
        *(uint4*)(Ks + r * QKS + gp * 8)     = w0;
        *(uint4*)(Ks + r * QKS + gp * 8 + 4) = w1;
    }
    __syncthreads();

    {
        float acc[5][2][4];
        #pragma unroll
        for (int i = 0; i < 5; i++)
            #pragma unroll
            for (int c = 0; c < 2; c++)
                #pragma unroll
                for (int r = 0; r < 4; r++) acc[i][c][r] = 0.f;

        #pragma unroll
        for (int ks = 0; ks < 8; ks++) {
            const int k0 = ks * 8 + 2 * t;
            unsigned af[5][4];
            #pragma unroll
            for (int i = 0; i < 5; i++) {
                int r = i * 16 + g;
                uint2 lo = *(const uint2*)(Qs + r * QKS + k0);
                uint2 hi = *(const uint2*)(Qs + (r + 8) * QKS + k0);
                af[i][0] = lo.x; af[i][2] = lo.y;
                af[i][1] = hi.x; af[i][3] = hi.y;
            }
            #pragma unroll
            for (int c = 0; c < 2; c++) {
                int n = (warp + 8 * c) * 8 + g;
                uint2 bb = *(const uint2*)(Ks + n * QKS + k0);
                #pragma unroll
                for (int i = 0; i < 5; i++)
                    MMA_TF32(acc[i][c], af[i][0], af[i][1], af[i][2], af[i][3],
                             bb.x, bb.y);
            }
        }
        #pragma unroll
        for (int c = 0; c < 2; c++) {
            int col = (warp + 8 * c) * 8 + 2 * t;
            #pragma unroll
            for (int i = 0; i < 5; i++) {
                int q0 = i * 16 + g;
                *(float2*)(Ss + q0 * SSTR + col) =
                    make_float2(acc[i][c][0], acc[i][c][1]);
                *(float2*)(Ss + (q0 + 8) * SSTR + col) =
                    make_float2(acc[i][c][2], acc[i][c][3]);
            }
        }
        const float k0v = Ks[128 * QKS + lane];
        const float k1v = Ks[128 * QKS + 32 + lane];
        for (int qr = warp; qr < NTOK; qr += 8) {
            float s = fmaf(Qs[qr * QKS + lane], k0v,
                           Qs[qr * QKS + 32 + lane] * k1v);
            #pragma unroll
            for (int o = 16; o; o >>= 1) s += __shfl_xor_sync(~0u, s, o);
            if (lane == 0) Ss[qr * SSTR + 128] = s;
        }
    }
    __syncthreads();

    {
        const float* vb = kb + CDIM;
        const uint32_t vbase = smem_u32(Vs);
        for (int idx = tid; idx < 129 * 16; idx += 256) {
            int m = idx >> 4, c = idx & 15;
            cp16s(vbase + (uint32_t)(m * QKS + c * 4) * 4,
                  vb + (size_t)m * 2048 + c * 4);
        }
        asm volatile("cp.async.commit_group;" ::: "memory");
    }

    {
        const int nW = *nW_ptr;
        const int mc = (nW < 2) ? nW : 2;
        const int w = b % nW;
        const bool use_l = (w < mc);
        const bool use_r = (w >= nW - mc);
        const int* ml = mask_l + (size_t)w * NTOK * MTOK;
        const int* mr = mask_r + (size_t)(2 - mc + (w - (nW - mc))) * NTOK * MTOK;
        const float scale = 0.125f;
        const float NEG = -3.402823466e38f;

        for (int qr = warp; qr < NTOK; qr += 8) {
            const int nm = (lane == 0) ? 5 : 4;
            float s[5];
            for (int j = 0; j < nm; j++) {
                const int m = lane + 32 * j;
                float a = Ss[qr * SSTR + m] * scale;
                float bias = (qr == 0)
                    ? ((m == 0) ? tb[191] : tb[192 + m - 1])
                    : ((m == 0) ? tb[320 + qr - 1] : tb[qr - m + 127]);
                a += bias;
                bool msk = false;
                if (use_l) msk = ml[qr * MTOK + m] != 0;
                if (use_r) msk = msk || (mr[qr * MTOK + m] != 0);
                s[j] = msk ? NEG : a;
            }
            float mx = s[0];
            for (int j = 1; j < nm; j++) mx = fmaxf(mx, s[j]);
            #pragma unroll
            for (int o = 16; o; o >>= 1) mx = fmaxf(mx, __shfl_xor_sync(~0u, mx, o));
            float sum = 0.f, p[5];
            for (int j = 0; j < nm; j++) { p[j] = __expf(s[j] - mx); sum += p[j]; }
            #pragma unroll
            for (int o = 16; o; o >>= 1) sum += __shfl_xor_sync(~0u, sum, o);
            const float inv = 1.f / sum;
            __syncwarp();
            for (int j = 0; j < nm; j++) {
                const int m = lane + 32 * j;
                const int pm = (m & ~7) | ((m & 3) << 1) | ((m >> 2) & 1);
                Ss[qr * SSTR + pm] = p[j] * inv;
            }
            if (lane < 7) Ss[qr * SSTR + 129 + lane] = 0.f;
        }
    }
    asm volatile("cp.async.wait_group 0;" ::: "memory");
    __syncthreads();

    {
        const int wc = warp * 8 + g;
        float acc[5][4];
        #pragma unroll
        for (int i = 0; i < 5; i++)
            #pragma unroll
            for (int r = 0; r < 4; r++) acc[i][r] = 0.f;

        #pragma unroll
        for (int ks = 0; ks < 17; ks++) {
            const int mrow = ks * 8 + t;
            const unsigned b0 = f2tf32(Vs[mrow * QKS + wc]);
            const unsigned b1 = f2tf32(Vs[(mrow + 4) * QKS + wc]);
            const int k0 = ks * 8 + 2 * t;
            #pragma unroll
            for (int i = 0; i < 5; i++) {
                int r = i * 16 + g;
                uint2 lo = *(const uint2*)(Ss + r * SSTR + k0);
                uint2 hi = *(const uint2*)(Ss + (r + 8) * SSTR + k0);
                MMA_TF32(acc[i], lo.x, hi.x, lo.y, hi.y, b0, b1);
            }
        }
        // output rounded + k-permuted for gemm_pp
        const int c0 = 2 * t, c1 = 2 * t + 1;
        const int p0 = ((c0 & 3) << 1) | ((c0 >> 2) & 1);
        const int p1 = ((c1 & 3) << 1) | ((c1 >> 2) & 1);
        const int colbase = h * HDIM + warp * 8;
        #pragma unroll
        for (int i = 0; i < 5; i++) {
            int q0 = i * 16 + g, q1 = q0 + 8;
            if (q0 < NTOK) {
                float* dst = ao + ((size_t)b * NTOK + q0) * CDIM + colbase;
                dst[p0] = __uint_as_float(f2tf32(acc[i][0]));
                dst[p1] = __uint_as_float(f2tf32(acc[i][1]));
            }
            if (q1 < NTOK) {
                float* dst = ao + ((size_t)b * NTOK + q1) * CDIM + colbase;
                dst[p0] = __uint_as_float(f2tf32(acc[i][2]));
                dst[p1] = __uint_as_float(f2tf32(acc[i][3]));
            }
        }
    }
}

// ---------------------------------------------------------------------------
extern "C" void kernel_launch(void* const* d_in, const int* in_sizes, int n_in,
                              void* d_out, int out_size)
{
    const float* x        = (const float*)d_in[0];
    const float* x_       = (const float*)d_in[1];
    const int*   mask_l   = (const int*)d_in[2];
    const int*   mask_r   = (const int*)d_in[3];
    const int*   nW_ptr   = (const int*)d_in[4];
    const float* Wq       = (const float*)d_in[5];
    const float* bq       = (const float*)d_in[6];
    const float* Wkv      = (const float*)d_in[7];
    const float* bkv      = (const float*)d_in[8];
    const float* Wp       = (const float*)d_in[9];
    const float* bp       = (const float*)d_in[10];
    const float* rel      = (const float*)d_in[11];
    const float* cls_self = (const float*)d_in[12];
    const float* cls_up   = (const float*)d_in[13];
    const float* cls_down = (const float*)d_in[14];

    const int BnW = in_sizes[0] / (NTOK * CDIM);   // 512
    const int Mq  = BnW * NTOK;                    // 33280
    const int Mkv = BnW * MTOK;                    // 66048

    float *qbuf, *kvbuf, *aobuf, *wqt, *wkvt, *wpt;
    cudaGetSymbolAddress((void**)&qbuf,  g_q);
    cudaGetSymbolAddress((void**)&kvbuf, g_kv);
    cudaGetSymbolAddress((void**)&aobuf, g_ao);
    cudaGetSymbolAddress((void**)&wqt,   g_wqt);
    cudaGetSymbolAddress((void**)&wkvt,  g_wkvt);
    cudaGetSymbolAddress((void**)&wpt,   g_wpt);

    transpose_tf32_perm<<<dim3(CDIM / 32, CDIM / 32), 256>>>(Wq, wqt, CDIM, CDIM);
    transpose_tf32_perm<<<dim3(2 * CDIM / 32, CDIM / 32), 256>>>(Wkv, wkvt, CDIM, 2 * CDIM);
    transpose_tf32_perm<<<dim3(CDIM / 32, CDIM / 32), 256>>>(Wp, wpt, CDIM, CDIM);

    const int gsm_raw = 2 * STAGE_W * sizeof(float);    // 77824
    const int gsm_pp  = 2 * PSTAGE_W * sizeof(float);   // 81920
    cudaFuncSetAttribute(gemm_raw, cudaFuncAttributeMaxDynamicSharedMemorySize, gsm_raw);
    cudaFuncSetAttribute(gemm_pp,  cudaFuncAttributeMaxDynamicSharedMemorySize, gsm_pp);

    gemm_raw<<<dim3(CDIM / 128, Mq / 128), 256, gsm_raw>>>(x, wqt, bq, qbuf, Mq, CDIM, CDIM);
    gemm_raw<<<dim3(2 * CDIM / 128, Mkv / 128), 256, gsm_raw>>>(x_, wkvt, bkv, kvbuf, Mkv, 2 * CDIM, CDIM);

    const int asm_bytes = ATTN_W * sizeof(float);
    cudaFuncSetAttribute(attn_tc, cudaFuncAttributeMaxDynamicSharedMemorySize, asm_bytes);
    attn_tc<<<dim3(NHEAD, BnW), 256, asm_bytes>>>(
        qbuf, kvbuf, mask_l, mask_r, nW_ptr, rel, cls_self, cls_up, cls_down, aobuf);

    gemm_pp<<<dim3(CDIM / 128, Mq / 128), 256, gsm_pp>>>(aobuf, wpt, bp, (float*)d_out, Mq, CDIM, CDIM);
}

// round 14
// speedup vs baseline: 1.0600x; 1.0600x over previous
#include <cuda_runtime.h>
#include <cuda_bf16.h>
#include <cstdint>

#define NTOK 65
#define MTOK 129
#define NHEAD 16
#define HDIM 64
#define CDIM 1024

// fp32 intermediates
__device__ float g_q [512 * NTOK * CDIM];
__device__ float g_kv[512 * MTOK * 2 * CDIM];
__device__ float g_ao[512 * NTOK * CDIM];     // tf32-rounded + k-permuted (attention)
// tf32-rounded, k-permuted weights [N][perm(K)]
__device__ float g_wqt [CDIM * CDIM];
__device__ float g_wkvt[2 * CDIM * CDIM];
__device__ float g_wpt [CDIM * CDIM];

__device__ __forceinline__ unsigned f2tf32(float x) {
    unsigned r;
    asm("cvt.rna.tf32.f32 %0, %1;" : "=r"(r) : "f"(x));
    return r;
}
__device__ __forceinline__ void cp16s(uint32_t s, const float* g) {
    asm volatile("cp.async.cg.shared.global [%0], [%1], 16;"
                 :: "r"(s), "l"(g) : "memory");
}
__device__ __forceinline__ uint32_t smem_u32(const void* p) {
    uint32_t a;
    asm("{ .reg .u64 t; cvta.to.shared.u64 t, %1; cvt.u32.u64 %0, t; }"
        : "=r"(a) : "l"(p));
    return a;
}
#define MMA_TF32(acc, a0, a1, a2, a3, b0, b1) \
    asm volatile( \
        "mma.sync.aligned.m16n8k8.row.col.f32.tf32.tf32.f32 " \
        "{%0,%1,%2,%3}, {%4,%5,%6,%7}, {%8,%9}, {%0,%1,%2,%3};" \
        : "+f"((acc)[0]), "+f"((acc)[1]), "+f"((acc)[2]), "+f"((acc)[3]) \
        : "r"(a0), "r"(a1), "r"(a2), "r"(a3), "r"(b0), "r"(b1))

// ---------------------------------------------------------------------------
// W[K][N] fp32 -> Wt[N][perm(K)] tf32-rounded; p(k)=(k&~7)|((k&3)<<1)|((k>>2)&1)
// ---------------------------------------------------------------------------
__global__ __launch_bounds__(256) void transpose_tf32_perm(
    const float* __restrict__ W, float* __restrict__ Wt, int K, int N)
{
    __shared__ float t[32][33];
    const int n0 = blockIdx.x * 32, k0 = blockIdx.y * 32;
    const int tx = threadIdx.x & 31, ty = threadIdx.x >> 5;
    #pragma unroll
    for (int i = 0; i < 4; i++)
        t[ty + 8 * i][tx] = W[(size_t)(k0 + ty + 8 * i) * N + n0 + tx];
    __syncthreads();
    const int pk = (tx & ~7) | ((tx & 3) << 1) | ((tx >> 2) & 1);
    #pragma unroll
    for (int i = 0; i < 4; i++)
        Wt[(size_t)(n0 + ty + 8 * i) * K + k0 + pk] =
            __uint_as_float(f2tf32(t[tx][ty + 8 * i]));
}

// ---------------------------------------------------------------------------
// GEMM variant 1 (raw A) — R11 structure verbatim.
// A: raw fp32, stride 36, scalar LDS + cvt.rna in-register.
// B: pre-rounded/permuted, stride 40, LDS.64.
// 128x128x32 tile, 8 warps 64x32, issue->wait(1)->sync, 2 CTA/SM.
// ---------------------------------------------------------------------------
#define AGS 36
#define BGS 40
#define A_WORDS (128 * AGS)
#define STAGE_W (A_WORDS + 128 * BGS)   // 9728 words

__global__ __launch_bounds__(256, 2) void gemm_raw(
    const float* __restrict__ A, const float* __restrict__ Bt,
    const float* __restrict__ bias, float* __restrict__ C,
    int M, int N, int K)
{
    extern __shared__ float smg[];

    const int tid  = threadIdx.x;
    const int lane = tid & 31;
    const int warp = tid >> 5;
    const int wm   = warp >> 2;
    const int wn   = warp & 3;
    const int g    = lane >> 2;
    const int t    = lane & 3;

    const int bn = blockIdx.x, bm = blockIdx.y;
    const float* Ag = A  + (size_t)bm * 128 * K;
    const float* Bg = Bt + (size_t)bn * 128 * K;
    const uint32_t sb = smem_u32(smg);

    float acc[4][4][4];
    #pragma unroll
    for (int i = 0; i < 4; i++)
        #pragma unroll
        for (int j = 0; j < 4; j++)
            #pragma unroll
            for (int r = 0; r < 4; r++) acc[i][j][r] = 0.f;

    auto issue = [&](int kt, int s) {
        const uint32_t base = sb + s * (STAGE_W * 4);
        #pragma unroll
        for (int it = 0; it < 8; it++) {
            int idx = tid + it * 256;
            int row = (idx >> 3) & 127, c = idx & 7;
            if (idx < 1024)
                cp16s(base + (row * AGS + c * 4) * 4,
                      Ag + (size_t)row * K + kt + c * 4);
            else
                cp16s(base + (A_WORDS + row * BGS + c * 4) * 4,
                      Bg + (size_t)row * K + kt + c * 4);
        }
        asm volatile("cp.async.commit_group;" ::: "memory");
    };

    issue(0, 0);
    const int NT = K >> 5;
    for (int ti = 0; ti < NT; ti++) {
        const int cur = ti & 1;
        if (ti + 1 < NT) {
            issue((ti + 1) << 5, cur ^ 1);
            asm volatile("cp.async.wait_group 1;" ::: "memory");
        } else {
            asm volatile("cp.async.wait_group 0;" ::: "memory");
        }
        __syncthreads();

        const float* As = smg + cur * STAGE_W;
        const float* Bs = As + A_WORDS;
        #pragma unroll
        for (int ks = 0; ks < 4; ks++) {
            const int kb = ks * 8;
            unsigned af[4][4];
            #pragma unroll
            for (int i = 0; i < 4; i++) {
                int r = wm * 64 + i * 16 + g;
                af[i][0] = f2tf32(As[r * AGS + kb + t]);
                af[i][1] = f2tf32(As[(r + 8) * AGS + kb + t]);
                af[i][2] = f2tf32(As[r * AGS + kb + t + 4]);
                af[i][3] = f2tf32(As[(r + 8) * AGS + kb + t + 4]);
            }
            unsigned bf[4][2];
            #pragma unroll
            for (int j = 0; j < 4; j++) {
                int n = wn * 32 + j * 8 + g;
                uint2 bb = *(const uint2*)(Bs + n * BGS + kb + 2 * t);
                bf[j][0] = bb.x; bf[j][1] = bb.y;
            }
            #pragma unroll
            for (int i = 0; i < 4; i++)
                #pragma unroll
                for (int j = 0; j < 4; j++)
                    MMA_TF32(acc[i][j], af[i][0], af[i][1], af[i][2], af[i][3],
                             bf[j][0], bf[j][1]);
        }
        __syncthreads();
    }

    #pragma unroll
    for (int i = 0; i < 4; i++) {
        int row0 = bm * 128 + wm * 64 + i * 16 + g;
        #pragma unroll
        for (int j = 0; j < 4; j++) {
            int col = bn * 128 + wn * 32 + j * 8 + t * 2;
            float b0 = bias[col], b1 = bias[col + 1];
            float2 v0 = make_float2(acc[i][j][0] + b0, acc[i][j][1] + b1);
            float2 v1 = make_float2(acc[i][j][2] + b0, acc[i][j][3] + b1);
            *(float2*)(C + (size_t)row0 * N + col)       = v0;
            *(float2*)(C + (size_t)(row0 + 8) * N + col) = v1;
        }
    }
}

// ---------------------------------------------------------------------------
// GEMM variant 2 (pre-permuted A) — same R11 loop structure, LDS.64 A frags.
// ---------------------------------------------------------------------------
#define PSTAGE_W (2 * 128 * BGS)        // 10240 words

__global__ __launch_bounds__(256, 2) void gemm_pp(
    const float* __restrict__ A, const float* __restrict__ Bt,
    const float* __restrict__ bias, float* __restrict__ C,
    int M, int N, int K)
{
    extern __shared__ float smg[];

    const int tid  = threadIdx.x;
    const int lane = tid & 31;
    const int warp = tid >> 5;
    const int wm   = warp >> 2;
    const int wn   = warp & 3;
    const int g    = lane >> 2;
    const int t    = lane & 3;

    const int bn = blockIdx.x, bm = blockIdx.y;
    const float* Ag = A  + (size_t)bm * 128 * K;
    const float* Bg = Bt + (size_t)bn * 128 * K;
    const uint32_t sb = smem_u32(smg);

    float acc[4][4][4];
    #pragma unroll
    for (int i = 0; i < 4; i++)
        #pragma unroll
        for (int j = 0; j < 4; j++)
            #pragma unroll
            for (int r = 0; r < 4; r++) acc[i][j][r] = 0.f;

    auto issue = [&](int kt, int s) {
        const uint32_t base = sb + s * (PSTAGE_W * 4);
        #pragma unroll
        for (int it = 0; it < 8; it++) {
            int idx = tid + it * 256;
            int row = (idx >> 3) & 127, c = idx & 7;
            if (idx < 1024)
                cp16s(base + (row * BGS + c * 4) * 4,
                      Ag + (size_t)row * K + kt + c * 4);
            else
                cp16s(base + ((128 * BGS) + row * BGS + c * 4) * 4,
                      Bg + (size_t)row * K + kt + c * 4);
        }
        asm volatile("cp.async.commit_group;" ::: "memory");
    };

    issue(0, 0);
    const int NT = K >> 5;
    for (int ti = 0; ti < NT; ti++) {
        const int cur = ti & 1;
        if (ti + 1 < NT) {
            issue((ti + 1) << 5, cur ^ 1);
            asm volatile("cp.async.wait_group 1;" ::: "memory");
        } else {
            asm volatile("cp.async.wait_group 0;" ::: "memory");
        }
        __syncthreads();

        const float* As = smg + cur * PSTAGE_W;
        const float* Bs = As + 128 * BGS;
        #pragma unroll
        for (int ks = 0; ks < 4; ks++) {
            const int k0 = ks * 8 + 2 * t;
            unsigned af[4][4];
            #pragma unroll
            for (int i = 0; i < 4; i++) {
                int r = wm * 64 + i * 16 + g;
                uint2 lo = *(const uint2*)(As + r * BGS + k0);
                uint2 hi = *(const uint2*)(As + (r + 8) * BGS + k0);
                af[i][0] = lo.x; af[i][2] = lo.y;
                af[i][1] = hi.x; af[i][3] = hi.y;
            }
            unsigned bf[4][2];
            #pragma unroll
            for (int j = 0; j < 4; j++) {
                int n = wn * 32 + j * 8 + g;
                uint2 bb = *(const uint2*)(Bs + n * BGS + k0);
                bf[j][0] = bb.x; bf[j][1] = bb.y;
            }
            #pragma unroll
            for (int i = 0; i < 4; i++)
                #pragma unroll
                for (int j = 0; j < 4; j++)
                    MMA_TF32(acc[i][j], af[i][0], af[i][1], af[i][2], af[i][3],
                             bf[j][0], bf[j][1]);
        }
        __syncthreads();
    }

    #pragma unroll
    for (int i = 0; i < 4; i++) {
        int row0 = bm * 128 + wm * 64 + i * 16 + g;
        #pragma unroll
        for (int j = 0; j < 4; j++) {
            int col = bn * 128 + wn * 32 + j * 8 + t * 2;
            float b0 = bias[col], b1 = bias[col + 1];
            float2 v0 = make_float2(acc[i][j][0] + b0, acc[i][j][1] + b1);
            float2 v1 = make_float2(acc[i][j][2] + b0, acc[i][j][3] + b1);
            *(float2*)(C + (size_t)row0 * N + col)       = v0;
            *(float2*)(C + (size_t)(row0 + 8) * N + col) = v1;
        }
    }
}

// ---------------------------------------------------------------------------
// Tensor-core attention (R11 core; output rounded + k-permuted for gemm_pp)
// ---------------------------------------------------------------------------
#define SSTR 136
#define QKS 72
#define OFF_Q (80 * SSTR)
#define OFF_K (OFF_Q + 80 * QKS)
#define OFF_TB (OFF_K + 129 * QKS)
#define ATTN_W (OFF_TB + 392)

__global__ __launch_bounds__(256, 2) void attn_tc(
    const float* __restrict__ q, const float* __restrict__ kv,
    const int* __restrict__ mask_l,
    const int* __restrict__ mask_r,
    const int* __restrict__ nW_ptr,
    const float* __restrict__ rel_table,
    const float* __restrict__ cls_self,
    const float* __restrict__ cls_up,
    const float* __restrict__ cls_down,
    float* __restrict__ ao)
{
    const int h = blockIdx.x;
    const int b = blockIdx.y;
    const int tid = threadIdx.x;
    const int lane = tid & 31;
    const int warp = tid >> 5;
    const int g = lane >> 2;
    const int t = lane & 3;

    extern __shared__ float sm[];
    float* Ss = sm;
    float* Qs = sm + OFF_Q;
    float* Ks = sm + OFF_K;
    float* Vs = sm + OFF_Q;               // overlay (after QK)
    float* tb = sm + OFF_TB;

    for (int i = tid; i < 191; i += 256) tb[i] = rel_table[i * NHEAD + h];
    if (tid == 0) tb[191] = cls_self[h];
    for (int i = tid; i < 128; i += 256) tb[192 + i] = cls_up[h * (MTOK - 1) + i];
    for (int i = tid; i < 64; i += 256) tb[320 + i] = cls_down[h * (NTOK - 1) + i];

    const float* qb = q + (size_t)b * NTOK * CDIM + h * HDIM;
    for (int idx = tid; idx < 65 * 8; idx += 256) {
        int r = idx >> 3, gp = idx & 7;
        const float* p = qb + (size_t)r * CDIM + gp * 8;
        float4 a = *(const float4*)p, c = *(const float4*)(p + 4);
        uint4 w0, w1;
        w0.x = f2tf32(a.x); w0.y = f2tf32(c.x); w0.z = f2tf32(a.y); w0.w = f2tf32(c.y);
        w1.x = f2tf32(a.z); w1.y = f2tf32(c.z); w1.z = f2tf32(a.w); w1.w = f2tf32(c.w);
        *(uint4*)(Qs + r * QKS + gp * 8)     = w0;
        *(uint4*)(Qs + r * QKS + gp * 8 + 4) = w1;
    }
    const float* kb = kv + (size_t)b * MTOK * 2 * CDIM + h * HDIM;
    for (int idx = tid; idx < 129 * 8; idx += 256) {
        int r = idx >> 3, gp = idx & 7;
        const float* p = kb + (size_t)r * 2048 + gp * 8;
        float4 a = *(const float4*)p, c = *(const float4*)(p + 4);
        uint4 w0, w1;
        w0.x = f2tf32(a.x); w0.y = f2tf32(c.x); w0.z = f2tf32(a.y); w0.w = f2tf32(c.y);
        w1.x = f2tf32(a.z); w1.y = f2tf32(c.z); w1.z = f2tf32(a.w); w1.w = f2tf32(c.w);
        *(uint4*)(Ks + r * QKS + gp * 8)     = w0;
        *(uint4*)(Ks + r * QKS + gp * 8 + 4) = w1;
    }
    __syncthreads();

    {
        float acc[5][2][4];
        #pragma unroll
        for (int i = 0; i < 5; i++)
            #pragma unroll
            for (int c = 0; c < 2; c++)
                #pragma unroll
                for (int r = 0; r < 4; r++) acc[i][c][r] = 0.f;

        #pragma unroll
        for (int ks = 0; ks < 8; ks++) {
            const int k0 = ks * 8 + 2 * t;
            unsigned af[5][4];
            #pragma unroll
            for (int i = 0; i < 5; i++) {
                int r = i * 16 + g;
                uint2 lo = *(const uint2*)(Qs + r * QKS + k0);
                uint2 hi = *(const uint2*)(Qs + (r + 8) * QKS + k0);
                af[i][0] = lo.x; af[i][2] = lo.y;
                af[i][1] = hi.x; af[i][3] = hi.y;
            }
            #pragma unroll
            for (int c = 0; c < 2; c++) {
                int n = (warp + 8 * c) * 8 + g;
                uint2 bb = *(const uint2*)(Ks + n * QKS + k0);
                #pragma unroll
                for (int i = 0; i < 5; i++)
                    MMA_TF32(acc[i][c], af[i][0], af[i][1], af[i][2], af[i][3],
                             bb.x, bb.y);
            }
        }
        #pragma unroll
        for (int c = 0; c < 2; c++) {
            int col = (warp + 8 * c) * 8 + 2 * t;
            #pragma unroll
            for (int i = 0; i < 5; i++) {
                int q0 = i * 16 + g;
                *(float2*)(Ss + q0 * SSTR + col) =
                    make_float2(acc[i][c][0], acc[i][c][1]);
                *(float2*)(Ss + (q0 + 8) * SSTR + col) =
                    make_float2(acc[i][c][2], acc[i][c][3]);
            }
        }
        const float k0v = Ks[128 * QKS + lane];
        const float k1v = Ks[128 * QKS + 32 + lane];
        for (int qr = warp; qr < NTOK; qr += 8) {
            float s = fmaf(Qs[qr * QKS + lane], k0v,
                           Qs[qr * QKS + 32 + lane] * k1v);
            #pragma unroll
            for (int o = 16; o; o >>= 1) s += __shfl_xor_sync(~0u, s, o);
            if (lane == 0) Ss[qr * SSTR + 128] = s;
        }
    }
    __syncthreads();

    {
        const float* vb = kb + CDIM;
        const uint32_t vbase = smem_u32(Vs);
        for (int idx = tid; idx < 129 * 16; idx += 256) {
            int m = idx >> 4, c = idx & 15;
            cp16s(vbase + (uint32_t)(m * QKS + c * 4) * 4,
                  vb + (size_t)m * 2048 + c * 4);
        }
        asm volatile("cp.async.commit_group;" ::: "memory");
    }

    {
        const int nW = *nW_ptr;
        const int mc = (nW < 2) ? nW : 2;
        const int w = b % nW;
        const bool use_l = (w < mc);
        const bool use_r = (w >= nW - mc);
        const int* ml = mask_l + (size_t)w * NTOK * MTOK;
        const int* mr = mask_r + (size_t)(2 - mc + (w - (nW - mc))) * NTOK * MTOK;
        const float scale = 0.125f;
        const float NEG = -3.402823466e38f;

        for (int qr = warp; qr < NTOK; qr += 8) {
            const int nm = (lane == 0) ? 5 : 4;
            float s[5];
            for (int j = 0; j < nm; j++) {
                const int m = lane + 32 * j;
                float a = Ss[qr * SSTR + m] * scale;
                float bias = (qr == 0)
                    ? ((m == 0) ? tb[191] : tb[192 + m - 1])
                    : ((m == 0) ? tb[320 + qr - 1] : tb[qr - m + 127]);
                a += bias;
                bool msk = false;
                if (use_l) msk = ml[qr * MTOK + m] != 0;
                if (use_r) msk = msk || (mr[qr * MTOK + m] != 0);
                s[j] = msk ? NEG : a;
            }
            float mx = s[0];
            for (int j = 1; j < nm; j++) mx = fmaxf(mx, s[j]);
            #pragma unroll
            for (int o = 16; o; o >>= 1) mx = fmaxf(mx, __shfl_xor_sync(~0u, mx, o));
            float sum = 0.f, p[5];
            for (int j = 0; j < nm; j++) { p[j] = __expf(s[j] - mx); sum += p[j]; }
            #pragma unroll
            for (int o = 16; o; o >>= 1) sum += __shfl_xor_sync(~0u, sum, o);
            const float inv = 1.f / sum;
            __syncwarp();
            for (int j = 0; j < nm; j++) {
                const int m = lane + 32 * j;
                const int pm = (m & ~7) | ((m & 3) << 1) | ((m >> 2) & 1);
                Ss[qr * SSTR + pm] = p[j] * inv;
            }
            if (lane < 7) Ss[qr * SSTR + 129 + lane] = 0.f;
        }
    }
    asm volatile("cp.async.wait_group 0;" ::: "memory");
    __syncthreads();

    {
        const int wc = warp * 8 + g;
        float acc[5][4];
        #pragma unroll
        for (int i = 0; i < 5; i++)
            #pragma unroll
            for (int r = 0; r < 4; r++) acc[i][r] = 0.f;

        #pragma unroll
        for (int ks = 0; ks < 17; ks++) {
            const int mrow = ks * 8 + t;
            const unsigned b0 = f2tf32(Vs[mrow * QKS + wc]);
            const unsigned b1 = f2tf32(Vs[(mrow + 4) * QKS + wc]);
            const int k0 = ks * 8 + 2 * t;
            #pragma unroll
            for (int i = 0; i < 5; i++) {
                int r = i * 16 + g;
                uint2 lo = *(const uint2*)(Ss + r * SSTR + k0);
                uint2 hi = *(const uint2*)(Ss + (r + 8) * SSTR + k0);
                MMA_TF32(acc[i], lo.x, hi.x, lo.y, hi.y, b0, b1);
            }
        }
        // output rounded + k-permuted for gemm_pp
        const int c0 = 2 * t, c1 = 2 * t + 1;
        const int p0 = ((c0 & 3) << 1) | ((c0 >> 2) & 1);
        const int p1 = ((c1 & 3) << 1) | ((c1 >> 2) & 1);
        const int colbase = h * HDIM + warp * 8;
        #pragma unroll
        for (int i = 0; i < 5; i++) {
            int q0 = i * 16 + g, q1 = q0 + 8;
            if (q0 < NTOK) {
                float* dst = ao + ((size_t)b * NTOK + q0) * CDIM + colbase;
                dst[p0] = __uint_as_float(f2tf32(acc[i][0]));
                dst[p1] = __uint_as_float(f2tf32(acc[i][1]));
            }
            if (q1 < NTOK) {
                float* dst = ao + ((size_t)b * NTOK + q1) * CDIM + colbase;
                dst[p0] = __uint_as_float(f2tf32(acc[i][2]));
                dst[p1] = __uint_as_float(f2tf32(acc[i][3]));
            }
        }
    }
}

// ---------------------------------------------------------------------------
extern "C" void kernel_launch(void* const* d_in, const int* in_sizes, int n_in,
                              void* d_out, int out_size)
{
    const float* x        = (const float*)d_in[0];
    const float* x_       = (const float*)d_in[1];
    const int*   mask_l   = (const int*)d_in[2];
    const int*   mask_r   = (const int*)d_in[3];
    const int*   nW_ptr   = (const int*)d_in[4];
    const float* Wq       = (const float*)d_in[5];
    const float* bq       = (const float*)d_in[6];
    const float* Wkv      = (const float*)d_in[7];
    const float* bkv      = (const float*)d_in[8];
    const float* Wp       = (const float*)d_in[9];
    const float* bp       = (const float*)d_in[10];
    const float* rel      = (const float*)d_in[11];
    const float* cls_self = (const float*)d_in[12];
    const float* cls_up   = (const float*)d_in[13];
    const float* cls_down = (const float*)d_in[14];

    const int BnW = in_sizes[0] / (NTOK * CDIM);   // 512
    const int Mq  = BnW * NTOK;                    // 33280
    const int Mkv = BnW * MTOK;                    // 66048

    float *qbuf, *kvbuf, *aobuf, *wqt, *wkvt, *wpt;
    cudaGetSymbolAddress((void**)&qbuf,  g_q);
    cudaGetSymbolAddress((void**)&kvbuf, g_kv);
    cudaGetSymbolAddress((void**)&aobuf, g_ao);
    cudaGetSymbolAddress((void**)&wqt,   g_wqt);
    cudaGetSymbolAddress((void**)&wkvt,  g_wkvt);
    cudaGetSymbolAddress((void**)&wpt,   g_wpt);

    transpose_tf32_perm<<<dim3(CDIM / 32, CDIM / 32), 256>>>(Wq, wqt, CDIM, CDIM);
    transpose_tf32_perm<<<dim3(2 * CDIM / 32, CDIM / 32), 256>>>(Wkv, wkvt, CDIM, 2 * CDIM);
    transpose_tf32_perm<<<dim3(CDIM / 32, CDIM / 32), 256>>>(Wp, wpt, CDIM, CDIM);

    const int gsm_raw = 2 * STAGE_W * sizeof(float);    // 77824
    const int gsm_pp  = 2 * PSTAGE_W * sizeof(float);   // 81920
    cudaFuncSetAttribute(gemm_raw, cudaFuncAttributeMaxDynamicSharedMemorySize, gsm_raw);
    cudaFuncSetAttribute(gemm_pp,  cudaFuncAttributeMaxDynamicSharedMemorySize, gsm_pp);

    gemm_raw<<<dim3(CDIM / 128, Mq / 128), 256, gsm_raw>>>(x, wqt, bq, qbuf, Mq, CDIM, CDIM);
    gemm_raw<<<dim3(2 * CDIM / 128, Mkv / 128), 256, gsm_raw>>>(x_, wkvt, bkv, kvbuf, Mkv, 2 * CDIM, CDIM);

    const int asm_bytes = ATTN_W * sizeof(float);
    cudaFuncSetAttribute(attn_tc, cudaFuncAttributeMaxDynamicSharedMemorySize, asm_bytes);
    attn_tc<<<dim3(NHEAD, BnW), 256, asm_bytes>>>(
        qbuf, kvbuf, mask_l, mask_r, nW_ptr, rel, cls_self, cls_up, cls_down, aobuf);

    gemm_pp<<<dim3(CDIM / 128, Mq / 128), 256, gsm_pp>>>(aobuf, wpt, bp, (float*)d_out, Mq, CDIM, CDIM);
}

// round 15
// speedup vs baseline: 1.0653x; 1.0050x over previous
#include <cuda_runtime.h>
#include <cuda_bf16.h>
#include <cstdint>

#define NTOK 65
#define MTOK 129
#define NHEAD 16
#define HDIM 64
#define CDIM 1024

// fp32 intermediates
__device__ float g_q [512 * NTOK * CDIM];
__device__ float g_kv[512 * MTOK * 2 * CDIM];
__device__ float g_ao[512 * NTOK * CDIM];     // raw fp32 (rounded in-GEMM)
// tf32-rounded, k-permuted weights [N][perm(K)]
__device__ float g_wqt [CDIM * CDIM];
__device__ float g_wkvt[2 * CDIM * CDIM];
__device__ float g_wpt [CDIM * CDIM];

__device__ __forceinline__ unsigned f2tf32(float x) {
    unsigned r;
    asm("cvt.rna.tf32.f32 %0, %1;" : "=r"(r) : "f"(x));
    return r;
}
__device__ __forceinline__ void cp16s(uint32_t s, const float* g) {
    asm volatile("cp.async.cg.shared.global [%0], [%1], 16;"
                 :: "r"(s), "l"(g) : "memory");
}
__device__ __forceinline__ uint32_t smem_u32(const void* p) {
    uint32_t a;
    asm("{ .reg .u64 t; cvta.to.shared.u64 t, %1; cvt.u32.u64 %0, t; }"
        : "=r"(a) : "l"(p));
    return a;
}
// streaming (evict-first) stores for write-once intermediates
__device__ __forceinline__ void st_cs2(float* p, float x, float y) {
    asm volatile("st.global.cs.v2.f32 [%0], {%1, %2};"
                 :: "l"(p), "f"(x), "f"(y) : "memory");
}
#define MMA_TF32(acc, a0, a1, a2, a3, b0, b1) \
    asm volatile( \
        "mma.sync.aligned.m16n8k8.row.col.f32.tf32.tf32.f32 " \
        "{%0,%1,%2,%3}, {%4,%5,%6,%7}, {%8,%9}, {%0,%1,%2,%3};" \
        : "+f"((acc)[0]), "+f"((acc)[1]), "+f"((acc)[2]), "+f"((acc)[3]) \
        : "r"(a0), "r"(a1), "r"(a2), "r"(a3), "r"(b0), "r"(b1))

// ---------------------------------------------------------------------------
// W[K][N] fp32 -> Wt[N][perm(K)] tf32-rounded; p(k)=(k&~7)|((k&3)<<1)|((k>>2)&1)
// ---------------------------------------------------------------------------
__global__ __launch_bounds__(256) void transpose_tf32_perm(
    const float* __restrict__ W, float* __restrict__ Wt, int K, int N)
{
    __shared__ float t[32][33];
    const int n0 = blockIdx.x * 32, k0 = blockIdx.y * 32;
    const int tx = threadIdx.x & 31, ty = threadIdx.x >> 5;
    #pragma unroll
    for (int i = 0; i < 4; i++)
        t[ty + 8 * i][tx] = W[(size_t)(k0 + ty + 8 * i) * N + n0 + tx];
    __syncthreads();
    const int pk = (tx & ~7) | ((tx & 3) << 1) | ((tx >> 2) & 1);
    #pragma unroll
    for (int i = 0; i < 4; i++)
        Wt[(size_t)(n0 + ty + 8 * i) * K + k0 + pk] =
            __uint_as_float(f2tf32(t[tx][ty + 8 * i]));
}

// ---------------------------------------------------------------------------
// tf32 mma.sync GEMM (R11 champion): C = A_raw @ Bt^T + bias
// A: raw fp32, stride 36, scalar LDS + cvt.rna in-register.
// B: pre-rounded/permuted, stride 40, LDS.64.
// 128x128x32 tile, 8 warps 64x32, issue->wait(1)->sync, 2 CTA/SM.
// Epilogue stores use st.global.cs (write-once streaming data).
// ---------------------------------------------------------------------------
#define AGS 36
#define BGS 40
#define A_WORDS (128 * AGS)
#define STAGE_W (A_WORDS + 128 * BGS)   // 9728 words

__global__ __launch_bounds__(256, 2) void gemm_raw(
    const float* __restrict__ A, const float* __restrict__ Bt,
    const float* __restrict__ bias, float* __restrict__ C,
    int M, int N, int K)
{
    extern __shared__ float smg[];

    const int tid  = threadIdx.x;
    const int lane = tid & 31;
    const int warp = tid >> 5;
    const int wm   = warp >> 2;
    const int wn   = warp & 3;
    const int g    = lane >> 2;
    const int t    = lane & 3;

    const int bn = blockIdx.x, bm = blockIdx.y;
    const float* Ag = A  + (size_t)bm * 128 * K;
    const float* Bg = Bt + (size_t)bn * 128 * K;
    const uint32_t sb = smem_u32(smg);

    float acc[4][4][4];
    #pragma unroll
    for (int i = 0; i < 4; i++)
        #pragma unroll
        for (int j = 0; j < 4; j++)
            #pragma unroll
            for (int r = 0; r < 4; r++) acc[i][j][r] = 0.f;

    auto issue = [&](int kt, int s) {
        const uint32_t base = sb + s * (STAGE_W * 4);
        #pragma unroll
        for (int it = 0; it < 8; it++) {
            int idx = tid + it * 256;
            int row = (idx >> 3) & 127, c = idx & 7;
            if (idx < 1024)
                cp16s(base + (row * AGS + c * 4) * 4,
                      Ag + (size_t)row * K + kt + c * 4);
            else
                cp16s(base + (A_WORDS + row * BGS + c * 4) * 4,
                      Bg + (size_t)row * K + kt + c * 4);
        }
        asm volatile("cp.async.commit_group;" ::: "memory");
    };

    issue(0, 0);
    const int NT = K >> 5;
    for (int ti = 0; ti < NT; ti++) {
        const int cur = ti & 1;
        if (ti + 1 < NT) {
            issue((ti + 1) << 5, cur ^ 1);
            asm volatile("cp.async.wait_group 1;" ::: "memory");
        } else {
            asm volatile("cp.async.wait_group 0;" ::: "memory");
        }
        __syncthreads();

        const float* As = smg + cur * STAGE_W;
        const float* Bs = As + A_WORDS;
        #pragma unroll
        for (int ks = 0; ks < 4; ks++) {
            const int kb = ks * 8;
            unsigned af[4][4];
            #pragma unroll
            for (int i = 0; i < 4; i++) {
                int r = wm * 64 + i * 16 + g;
                af[i][0] = f2tf32(As[r * AGS + kb + t]);
                af[i][1] = f2tf32(As[(r + 8) * AGS + kb + t]);
                af[i][2] = f2tf32(As[r * AGS + kb + t + 4]);
                af[i][3] = f2tf32(As[(r + 8) * AGS + kb + t + 4]);
            }
            unsigned bf[4][2];
            #pragma unroll
            for (int j = 0; j < 4; j++) {
                int n = wn * 32 + j * 8 + g;
                uint2 bb = *(const uint2*)(Bs + n * BGS + kb + 2 * t);
                bf[j][0] = bb.x; bf[j][1] = bb.y;
            }
            #pragma unroll
            for (int i = 0; i < 4; i++)
                #pragma unroll
                for (int j = 0; j < 4; j++)
                    MMA_TF32(acc[i][j], af[i][0], af[i][1], af[i][2], af[i][3],
                             bf[j][0], bf[j][1]);
        }
        __syncthreads();
    }

    #pragma unroll
    for (int i = 0; i < 4; i++) {
        int row0 = bm * 128 + wm * 64 + i * 16 + g;
        #pragma unroll
        for (int j = 0; j < 4; j++) {
            int col = bn * 128 + wn * 32 + j * 8 + t * 2;
            float b0 = bias[col], b1 = bias[col + 1];
            st_cs2(C + (size_t)row0 * N + col,
                   acc[i][j][0] + b0, acc[i][j][1] + b1);
            st_cs2(C + (size_t)(row0 + 8) * N + col,
                   acc[i][j][2] + b0, acc[i][j][3] + b1);
        }
    }
}

// ---------------------------------------------------------------------------
// Tensor-core attention v3 (R11 verbatim; ao stores use st.global.cs)
// ---------------------------------------------------------------------------
#define SSTR 136
#define QKS 72
#define OFF_Q (80 * SSTR)
#define OFF_K (OFF_Q + 80 * QKS)
#define OFF_TB (OFF_K + 129 * QKS)
#define ATTN_W (OFF_TB + 392)

__global__ __launch_bounds__(256, 2) void attn_tc(
    const float* __restrict__ q, const float* __restrict__ kv,
    const int* __restrict__ mask_l,
    const int* __restrict__ mask_r,
    const int* __restrict__ nW_ptr,
    const float* __restrict__ rel_table,
    const float* __restrict__ cls_self,
    const float* __restrict__ cls_up,
    const float* __restrict__ cls_down,
    float* __restrict__ ao)
{
    const int h = blockIdx.x;
    const int b = blockIdx.y;
    const int tid = threadIdx.x;
    const int lane = tid & 31;
    const int warp = tid >> 5;
    const int g = lane >> 2;
    const int t = lane & 3;

    extern __shared__ float sm[];
    float* Ss = sm;
    float* Qs = sm + OFF_Q;
    float* Ks = sm + OFF_K;
    float* Vs = sm + OFF_Q;               // overlay (after QK)
    float* tb = sm + OFF_TB;

    for (int i = tid; i < 191; i += 256) tb[i] = rel_table[i * NHEAD + h];
    if (tid == 0) tb[191] = cls_self[h];
    for (int i = tid; i < 128; i += 256) tb[192 + i] = cls_up[h * (MTOK - 1) + i];
    for (int i = tid; i < 64; i += 256) tb[320 + i] = cls_down[h * (NTOK - 1) + i];

    const float* qb = q + (size_t)b * NTOK * CDIM + h * HDIM;
    for (int idx = tid; idx < 65 * 8; idx += 256) {
        int r = idx >> 3, gp = idx & 7;
        const float* p = qb + (size_t)r * CDIM + gp * 8;
        float4 a = *(const float4*)p, c = *(const float4*)(p + 4);
        uint4 w0, w1;
        w0.x = f2tf32(a.x); w0.y = f2tf32(c.x); w0.z = f2tf32(a.y); w0.w = f2tf32(c.y);
        w1.x = f2tf32(a.z); w1.y = f2tf32(c.z); w1.z = f2tf32(a.w); w1.w = f2tf32(c.w);
        *(uint4*)(Qs + r * QKS + gp * 8)     = w0;
        *(uint4*)(Qs + r * QKS + gp * 8 + 4) = w1;
    }
    const float* kb = kv + (size_t)b * MTOK * 2 * CDIM + h * HDIM;
    for (int idx = tid; idx < 129 * 8; idx += 256) {
        int r = idx >> 3, gp = idx & 7;
        const float* p = kb + (size_t)r * 2048 + gp * 8;
        float4 a = *(const float4*)p, c = *(const float4*)(p + 4);
        uint4 w0, w1;
        w0.x = f2tf32(a.x); w0.y = f2tf32(c.x); w0.z = f2tf32(a.y); w0.w = f2tf32(c.y);
        w1.x = f2tf32(a.z); w1.y = f2tf32(c.z); w1.z = f2tf32(a.w); w1.w = f2tf32(c.w);
        *(uint4*)(Ks + r * QKS + gp * 8)     = w0;
        *(uint4*)(Ks + r * QKS + gp * 8 + 4) = w1;
    }
    __syncthreads();

    {
        float acc[5][2][4];
        #pragma unroll
        for (int i = 0; i < 5; i++)
            #pragma unroll
            for (int c = 0; c < 2; c++)
                #pragma unroll
                for (int r = 0; r < 4; r++) acc[i][c][r] = 0.f;

        #pragma unroll
        for (int ks = 0; ks < 8; ks++) {
            const int k0 = ks * 8 + 2 * t;
            unsigned af[5][4];
            #pragma unroll
            for (int i = 0; i < 5; i++) {
                int r = i * 16 + g;
                uint2 lo = *(const uint2*)(Qs + r * QKS + k0);
                uint2 hi = *(const uint2*)(Qs + (r + 8) * QKS + k0);
                af[i][0] = lo.x; af[i][2] = lo.y;
                af[i][1] = hi.x; af[i][3] = hi.y;
            }
            #pragma unroll
            for (int c = 0; c < 2; c++) {
                int n = (warp + 8 * c) * 8 + g;
                uint2 bb = *(const uint2*)(Ks + n * QKS + k0);
                #pragma unroll
                for (int i = 0; i < 5; i++)
                    MMA_TF32(acc[i][c], af[i][0], af[i][1], af[i][2], af[i][3],
                             bb.x, bb.y);
            }
        }
        #pragma unroll
        for (int c = 0; c < 2; c++) {
            int col = (warp + 8 * c) * 8 + 2 * t;
            #pragma unroll
            for (int i = 0; i < 5; i++) {
                int q0 = i * 16 + g;
                *(float2*)(Ss + q0 * SSTR + col) =
                    make_float2(acc[i][c][0], acc[i][c][1]);
                *(float2*)(Ss + (q0 + 8) * SSTR + col) =
                    make_float2(acc[i][c][2], acc[i][c][3]);
            }
        }
        const float k0v = Ks[128 * QKS + lane];
        const float k1v = Ks[128 * QKS + 32 + lane];
        for (int qr = warp; qr < NTOK; qr += 8) {
            float s = fmaf(Qs[qr * QKS + lane], k0v,
                           Qs[qr * QKS + 32 + lane] * k1v);
            #pragma unroll
            for (int o = 16; o; o >>= 1) s += __shfl_xor_sync(~0u, s, o);
            if (lane == 0) Ss[qr * SSTR + 128] = s;
        }
    }
    __syncthreads();

    {
        const float* vb = kb + CDIM;
        const uint32_t vbase = smem_u32(Vs);
        for (int idx = tid; idx < 129 * 16; idx += 256) {
            int m = idx >> 4, c = idx & 15;
            cp16s(vbase + (uint32_t)(m * QKS + c * 4) * 4,
                  vb + (size_t)m * 2048 + c * 4);
        }
        asm volatile("cp.async.commit_group;" ::: "memory");
    }

    {
        const int nW = *nW_ptr;
        const int mc = (nW < 2) ? nW : 2;
        const int w = b % nW;
        const bool use_l = (w < mc);
        const bool use_r = (w >= nW - mc);
        const int* ml = mask_l + (size_t)w * NTOK * MTOK;
        const int* mr = mask_r + (size_t)(2 - mc + (w - (nW - mc))) * NTOK * MTOK;
        const float scale = 0.125f;
        const float NEG = -3.402823466e38f;

        for (int qr = warp; qr < NTOK; qr += 8) {
            const int nm = (lane == 0) ? 5 : 4;
            float s[5];
            for (int j = 0; j < nm; j++) {
                const int m = lane + 32 * j;
                float a = Ss[qr * SSTR + m] * scale;
                float bias = (qr == 0)
                    ? ((m == 0) ? tb[191] : tb[192 + m - 1])
                    : ((m == 0) ? tb[320 + qr - 1] : tb[qr - m + 127]);
                a += bias;
                bool msk = false;
                if (use_l) msk = ml[qr * MTOK + m] != 0;
                if (use_r) msk = msk || (mr[qr * MTOK + m] != 0);
                s[j] = msk ? NEG : a;
            }
            float mx = s[0];
            for (int j = 1; j < nm; j++) mx = fmaxf(mx, s[j]);
            #pragma unroll
            for (int o = 16; o; o >>= 1) mx = fmaxf(mx, __shfl_xor_sync(~0u, mx, o));
            float sum = 0.f, p[5];
            for (int j = 0; j < nm; j++) { p[j] = __expf(s[j] - mx); sum += p[j]; }
            #pragma unroll
            for (int o = 16; o; o >>= 1) sum += __shfl_xor_sync(~0u, sum, o);
            const float inv = 1.f / sum;
            __syncwarp();
            for (int j = 0; j < nm; j++) {
                const int m = lane + 32 * j;
                const int pm = (m & ~7) | ((m & 3) << 1) | ((m >> 2) & 1);
                Ss[qr * SSTR + pm] = p[j] * inv;
            }
            if (lane < 7) Ss[qr * SSTR + 129 + lane] = 0.f;
        }
    }
    asm volatile("cp.async.wait_group 0;" ::: "memory");
    __syncthreads();

    {
        const int wc = warp * 8 + g;
        float acc[5][4];
        #pragma unroll
        for (int i = 0; i < 5; i++)
            #pragma unroll
            for (int r = 0; r < 4; r++) acc[i][r] = 0.f;

        #pragma unroll
        for (int ks = 0; ks < 17; ks++) {
            const int mrow = ks * 8 + t;
            const unsigned b0 = f2tf32(Vs[mrow * QKS + wc]);
            const unsigned b1 = f2tf32(Vs[(mrow + 4) * QKS + wc]);
            const int k0 = ks * 8 + 2 * t;
            #pragma unroll
            for (int i = 0; i < 5; i++) {
                int r = i * 16 + g;
                uint2 lo = *(const uint2*)(Ss + r * SSTR + k0);
                uint2 hi = *(const uint2*)(Ss + (r + 8) * SSTR + k0);
                MMA_TF32(acc[i], lo.x, hi.x, lo.y, hi.y, b0, b1);
            }
        }
        // output raw fp32 (rounded in downstream GEMM), streaming store
        const int colbase = h * HDIM + warp * 8 + 2 * t;
        #pragma unroll
        for (int i = 0; i < 5; i++) {
            int q0 = i * 16 + g, q1 = q0 + 8;
            if (q0 < NTOK)
                st_cs2(ao + ((size_t)b * NTOK + q0) * CDIM + colbase,
                       acc[i][0], acc[i][1]);
            if (q1 < NTOK)
                st_cs2(ao + ((size_t)b * NTOK + q1) * CDIM + colbase,
                       acc[i][2], acc[i][3]);
        }
    }
}

// ---------------------------------------------------------------------------
extern "C" void kernel_launch(void* const* d_in, const int* in_sizes, int n_in,
                              void* d_out, int out_size)
{
    const float* x        = (const float*)d_in[0];
    const float* x_       = (const float*)d_in[1];
    const int*   mask_l   = (const int*)d_in[2];
    const int*   mask_r   = (const int*)d_in[3];
    const int*   nW_ptr   = (const int*)d_in[4];
    const float* Wq       = (const float*)d_in[5];
    const float* bq       = (const float*)d_in[6];
    const float* Wkv      = (const float*)d_in[7];
    const float* bkv      = (const float*)d_in[8];
    const float* Wp       = (const float*)d_in[9];
    const float* bp       = (const float*)d_in[10];
    const float* rel      = (const float*)d_in[11];
    const float* cls_self = (const float*)d_in[12];
    const float* cls_up   = (const float*)d_in[13];
    const float* cls_down = (const float*)d_in[14];

    const int BnW = in_sizes[0] / (NTOK * CDIM);   // 512
    const int Mq  = BnW * NTOK;                    // 33280
    const int Mkv = BnW * MTOK;                    // 66048

    float *qbuf, *kvbuf, *aobuf, *wqt, *wkvt, *wpt;
    cudaGetSymbolAddress((void**)&qbuf,  g_q);
    cudaGetSymbolAddress((void**)&kvbuf, g_kv);
    cudaGetSymbolAddress((void**)&aobuf, g_ao);
    cudaGetSymbolAddress((void**)&wqt,   g_wqt);
    cudaGetSymbolAddress((void**)&wkvt,  g_wkvt);
    cudaGetSymbolAddress((void**)&wpt,   g_wpt);

    transpose_tf32_perm<<<dim3(CDIM / 32, CDIM / 32), 256>>>(Wq, wqt, CDIM, CDIM);
    transpose_tf32_perm<<<dim3(2 * CDIM / 32, CDIM / 32), 256>>>(Wkv, wkvt, CDIM, 2 * CDIM);
    transpose_tf32_perm<<<dim3(CDIM / 32, CDIM / 32), 256>>>(Wp, wpt, CDIM, CDIM);

    const int gsm = 2 * STAGE_W * sizeof(float);   // 77824
    cudaFuncSetAttribute(gemm_raw, cudaFuncAttributeMaxDynamicSharedMemorySize, gsm);

    gemm_raw<<<dim3(CDIM / 128, Mq / 128), 256, gsm>>>(x, wqt, bq, qbuf, Mq, CDIM, CDIM);
    gemm_raw<<<dim3(2 * CDIM / 128, Mkv / 128), 256, gsm>>>(x_, wkvt, bkv, kvbuf, Mkv, 2 * CDIM, CDIM);

    const int asm_bytes = ATTN_W * sizeof(float);
    cudaFuncSetAttribute(attn_tc, cudaFuncAttributeMaxDynamicSharedMemorySize, asm_bytes);
    attn_tc<<<dim3(NHEAD, BnW), 256, asm_bytes>>>(
        qbuf, kvbuf, mask_l, mask_r, nW_ptr, rel, cls_self, cls_up, cls_down, aobuf);

    gemm_raw<<<dim3(CDIM / 128, Mq / 128), 256, gsm>>>(aobuf, wpt, bp, (float*)d_out, Mq, CDIM, CDIM);
}

// round 16
// speedup vs baseline: 1.0981x; 1.0308x over previous
#include <cuda_runtime.h>
#include <cuda_bf16.h>
#include <cstdint>

#define NTOK 65
#define MTOK 129
#define NHEAD 16
#define HDIM 64
#define CDIM 1024

// fp32 intermediates
__device__ float g_q [512 * NTOK * CDIM];
__device__ float g_kv[512 * MTOK * 2 * CDIM];
__device__ float g_ao[512 * NTOK * CDIM];     // raw fp32 (rounded in-GEMM)
// tf32-rounded, k-permuted weights [N][perm(K)]
__device__ float g_wqt [CDIM * CDIM];
__device__ float g_wkvt[2 * CDIM * CDIM];
__device__ float g_wpt [CDIM * CDIM];

__device__ __forceinline__ unsigned f2tf32(float x) {
    unsigned r;
    asm("cvt.rna.tf32.f32 %0, %1;" : "=r"(r) : "f"(x));
    return r;
}
__device__ __forceinline__ void cp16s(uint32_t s, const float* g) {
    asm volatile("cp.async.cg.shared.global [%0], [%1], 16;"
                 :: "r"(s), "l"(g) : "memory");
}
__device__ __forceinline__ uint32_t smem_u32(const void* p) {
    uint32_t a;
    asm("{ .reg .u64 t; cvta.to.shared.u64 t, %1; cvt.u32.u64 %0, t; }"
        : "=r"(a) : "l"(p));
    return a;
}
__device__ __forceinline__ void st_cs2(float* p, float x, float y) {
    asm volatile("st.global.cs.v2.f32 [%0], {%1, %2};"
                 :: "l"(p), "f"(x), "f"(y) : "memory");
}
#define MMA_TF32(acc, a0, a1, a2, a3, b0, b1) \
    asm volatile( \
        "mma.sync.aligned.m16n8k8.row.col.f32.tf32.tf32.f32 " \
        "{%0,%1,%2,%3}, {%4,%5,%6,%7}, {%8,%9}, {%0,%1,%2,%3};" \
        : "+f"((acc)[0]), "+f"((acc)[1]), "+f"((acc)[2]), "+f"((acc)[3]) \
        : "r"(a0), "r"(a1), "r"(a2), "r"(a3), "r"(b0), "r"(b1))

// ---------------------------------------------------------------------------
// W[K][N] fp32 -> Wt[N][perm(K)] tf32-rounded; p(k)=(k&~7)|((k&3)<<1)|((k>>2)&1)
// ---------------------------------------------------------------------------
__global__ __launch_bounds__(256) void transpose_tf32_perm(
    const float* __restrict__ W, float* __restrict__ Wt, int K, int N)
{
    __shared__ float t[32][33];
    const int n0 = blockIdx.x * 32, k0 = blockIdx.y * 32;
    const int tx = threadIdx.x & 31, ty = threadIdx.x >> 5;
    #pragma unroll
    for (int i = 0; i < 4; i++)
        t[ty + 8 * i][tx] = W[(size_t)(k0 + ty + 8 * i) * N + n0 + tx];
    __syncthreads();
    const int pk = (tx & ~7) | ((tx & 3) << 1) | ((tx >> 2) & 1);
    #pragma unroll
    for (int i = 0; i < 4; i++)
        Wt[(size_t)(n0 + ty + 8 * i) * K + k0 + pk] =
            __uint_as_float(f2tf32(t[tx][ty + 8 * i]));
}

// ---------------------------------------------------------------------------
// tf32 mma.sync GEMM (R15 champion, unchanged)
// ---------------------------------------------------------------------------
#define AGS 36
#define BGS 40
#define A_WORDS (128 * AGS)
#define STAGE_W (A_WORDS + 128 * BGS)

__global__ __launch_bounds__(256, 2) void gemm_raw(
    const float* __restrict__ A, const float* __restrict__ Bt,
    const float* __restrict__ bias, float* __restrict__ C,
    int M, int N, int K)
{
    extern __shared__ float smg[];

    const int tid  = threadIdx.x;
    const int lane = tid & 31;
    const int warp = tid >> 5;
    const int wm   = warp >> 2;
    const int wn   = warp & 3;
    const int g    = lane >> 2;
    const int t    = lane & 3;

    const int bn = blockIdx.x, bm = blockIdx.y;
    const float* Ag = A  + (size_t)bm * 128 * K;
    const float* Bg = Bt + (size_t)bn * 128 * K;
    const uint32_t sb = smem_u32(smg);

    float acc[4][4][4];
    #pragma unroll
    for (int i = 0; i < 4; i++)
        #pragma unroll
        for (int j = 0; j < 4; j++)
            #pragma unroll
            for (int r = 0; r < 4; r++) acc[i][j][r] = 0.f;

    auto issue = [&](int kt, int s) {
        const uint32_t base = sb + s * (STAGE_W * 4);
        #pragma unroll
        for (int it = 0; it < 8; it++) {
            int idx = tid + it * 256;
            int row = (idx >> 3) & 127, c = idx & 7;
            if (idx < 1024)
                cp16s(base + (row * AGS + c * 4) * 4,
                      Ag + (size_t)row * K + kt + c * 4);
            else
                cp16s(base + (A_WORDS + row * BGS + c * 4) * 4,
                      Bg + (size_t)row * K + kt + c * 4);
        }
        asm volatile("cp.async.commit_group;" ::: "memory");
    };

    issue(0, 0);
    const int NT = K >> 5;
    for (int ti = 0; ti < NT; ti++) {
        const int cur = ti & 1;
        if (ti + 1 < NT) {
            issue((ti + 1) << 5, cur ^ 1);
            asm volatile("cp.async.wait_group 1;" ::: "memory");
        } else {
            asm volatile("cp.async.wait_group 0;" ::: "memory");
        }
        __syncthreads();

        const float* As = smg + cur * STAGE_W;
        const float* Bs = As + A_WORDS;
        #pragma unroll
        for (int ks = 0; ks < 4; ks++) {
            const int kb = ks * 8;
            unsigned af[4][4];
            #pragma unroll
            for (int i = 0; i < 4; i++) {
                int r = wm * 64 + i * 16 + g;
                af[i][0] = f2tf32(As[r * AGS + kb + t]);
                af[i][1] = f2tf32(As[(r + 8) * AGS + kb + t]);
                af[i][2] = f2tf32(As[r * AGS + kb + t + 4]);
                af[i][3] = f2tf32(As[(r + 8) * AGS + kb + t + 4]);
            }
            unsigned bf[4][2];
            #pragma unroll
            for (int j = 0; j < 4; j++) {
                int n = wn * 32 + j * 8 + g;
                uint2 bb = *(const uint2*)(Bs + n * BGS + kb + 2 * t);
                bf[j][0] = bb.x; bf[j][1] = bb.y;
            }
            #pragma unroll
            for (int i = 0; i < 4; i++)
                #pragma unroll
                for (int j = 0; j < 4; j++)
                    MMA_TF32(acc[i][j], af[i][0], af[i][1], af[i][2], af[i][3],
                             bf[j][0], bf[j][1]);
        }
        __syncthreads();
    }

    #pragma unroll
    for (int i = 0; i < 4; i++) {
        int row0 = bm * 128 + wm * 64 + i * 16 + g;
        #pragma unroll
        for (int j = 0; j < 4; j++) {
            int col = bn * 128 + wn * 32 + j * 8 + t * 2;
            float b0 = bias[col], b1 = bias[col + 1];
            st_cs2(C + (size_t)row0 * N + col,
                   acc[i][j][0] + b0, acc[i][j][1] + b1);
            st_cs2(C + (size_t)(row0 + 8) * N + col,
                   acc[i][j][2] + b0, acc[i][j][3] + b1);
        }
    }
}

// ---------------------------------------------------------------------------
// Tensor-core attention v4: Q/K staged RAW via cp.async (stride 68, no
// permute/cvt at staging — dot products are permutation-invariant when both
// operands share the mapping, and cvt.rna moves to fragment load). V via
// cp.async (stride 72) overlapped with softmax; pad rows zeroed (NaN safety).
// ---------------------------------------------------------------------------
#define SSTR 136
#define QS2 68
#define VQS 72
#define OFF_Q (80 * SSTR)                 // 10880
#define OFF_K (OFF_Q + 80 * QS2)          // 16320
#define OFF_TB (OFF_K + 129 * QS2)        // 25092
#define ATTN_W (OFF_TB + 392)             // 25484 words = 101936 B

__global__ __launch_bounds__(256, 2) void attn_tc(
    const float* __restrict__ q, const float* __restrict__ kv,
    const int* __restrict__ mask_l,
    const int* __restrict__ mask_r,
    const int* __restrict__ nW_ptr,
    const float* __restrict__ rel_table,
    const float* __restrict__ cls_self,
    const float* __restrict__ cls_up,
    const float* __restrict__ cls_down,
    float* __restrict__ ao)
{
    const int h = blockIdx.x;
    const int b = blockIdx.y;
    const int tid = threadIdx.x;
    const int lane = tid & 31;
    const int warp = tid >> 5;
    const int g = lane >> 2;
    const int t = lane & 3;

    extern __shared__ float sm[];
    float* Ss = sm;                       // [80][136]
    float* Qs = sm + OFF_Q;               // [80][68] raw fp32 (65 filled)
    float* Ks = sm + OFF_K;               // [129][68] raw fp32
    float* Vs = sm + OFF_Q;               // [136][72] overlay (after QK)
    float* tb = sm + OFF_TB;

    // issue Q/K cp.async first (raw, no cvt) — overlaps with table loads
    const float* qb = q + (size_t)b * NTOK * CDIM + h * HDIM;
    const float* kb = kv + (size_t)b * MTOK * 2 * CDIM + h * HDIM;
    {
        const uint32_t qbase = smem_u32(Qs);
        for (int idx = tid; idx < 65 * 16; idx += 256) {
            int m = idx >> 4, c = idx & 15;
            cp16s(qbase + (uint32_t)(m * QS2 + c * 4) * 4,
                  qb + (size_t)m * CDIM + c * 4);
        }
        const uint32_t kbase = smem_u32(Ks);
        for (int idx = tid; idx < 129 * 16; idx += 256) {
            int m = idx >> 4, c = idx & 15;
            cp16s(kbase + (uint32_t)(m * QS2 + c * 4) * 4,
                  kb + (size_t)m * 2048 + c * 4);
        }
        asm volatile("cp.async.commit_group;" ::: "memory");
    }

    // bias tables (LDG, overlapped with the async copies)
    for (int i = tid; i < 191; i += 256) tb[i] = rel_table[i * NHEAD + h];
    if (tid == 0) tb[191] = cls_self[h];
    for (int i = tid; i < 128; i += 256) tb[192 + i] = cls_up[h * (MTOK - 1) + i];
    for (int i = tid; i < 64; i += 256) tb[320 + i] = cls_down[h * (NTOK - 1) + i];

    asm volatile("cp.async.wait_group 0;" ::: "memory");
    __syncthreads();

    // ---- QK^T mma on raw operands, cvt.rna at fragment load ----
    {
        float acc[5][2][4];
        #pragma unroll
        for (int i = 0; i < 5; i++)
            #pragma unroll
            for (int c = 0; c < 2; c++)
                #pragma unroll
                for (int r = 0; r < 4; r++) acc[i][c][r] = 0.f;

        #pragma unroll
        for (int ks = 0; ks < 8; ks++) {
            const int kb0 = ks * 8;
            unsigned af[5][4];
            #pragma unroll
            for (int i = 0; i < 5; i++) {
                int r = i * 16 + g;
                af[i][0] = f2tf32(Qs[r * QS2 + kb0 + t]);
                af[i][1] = f2tf32(Qs[(r + 8) * QS2 + kb0 + t]);
                af[i][2] = f2tf32(Qs[r * QS2 + kb0 + t + 4]);
                af[i][3] = f2tf32(Qs[(r + 8) * QS2 + kb0 + t + 4]);
            }
            #pragma unroll
            for (int c = 0; c < 2; c++) {
                int n = (warp + 8 * c) * 8 + g;
                const unsigned b0 = f2tf32(Ks[n * QS2 + kb0 + t]);
                const unsigned b1 = f2tf32(Ks[n * QS2 + kb0 + t + 4]);
                #pragma unroll
                for (int i = 0; i < 5; i++)
                    MMA_TF32(acc[i][c], af[i][0], af[i][1], af[i][2], af[i][3],
                             b0, b1);
            }
        }
        #pragma unroll
        for (int c = 0; c < 2; c++) {
            int col = (warp + 8 * c) * 8 + 2 * t;
            #pragma unroll
            for (int i = 0; i < 5; i++) {
                int q0 = i * 16 + g;
                *(float2*)(Ss + q0 * SSTR + col) =
                    make_float2(acc[i][c][0], acc[i][c][1]);
                *(float2*)(Ss + (q0 + 8) * SSTR + col) =
                    make_float2(acc[i][c][2], acc[i][c][3]);
            }
        }
        // col 128 via SIMT dot on raw values
        const float k0v = Ks[128 * QS2 + lane];
        const float k1v = Ks[128 * QS2 + 32 + lane];
        for (int qr = warp; qr < NTOK; qr += 8) {
            float s = fmaf(Qs[qr * QS2 + lane], k0v,
                           Qs[qr * QS2 + 32 + lane] * k1v);
            #pragma unroll
            for (int o = 16; o; o >>= 1) s += __shfl_xor_sync(~0u, s, o);
            if (lane == 0) Ss[qr * SSTR + 128] = s;
        }
    }
    __syncthreads();   // Q,K dead; Ss holds scores

    // ---- V cp.async into overlay (raw fp32, stride 72); zero pad rows ----
    {
        const float* vb = kb + CDIM;
        const uint32_t vbase = smem_u32(Vs);
        for (int idx = tid; idx < 129 * 16; idx += 256) {
            int m = idx >> 4, c = idx & 15;
            cp16s(vbase + (uint32_t)(m * VQS + c * 4) * 4,
                  vb + (size_t)m * 2048 + c * 4);
        }
        asm volatile("cp.async.commit_group;" ::: "memory");
        // rows 129..135 can land on stride-pad words (NaN risk) — zero them.
        // Disjoint from the cp.async destination rows, so no race.
        for (int i = tid; i < 7 * VQS; i += 256) Vs[129 * VQS + i] = 0.f;
    }

    // ---- softmax + bias + mask (overlapped with V loads) ----
    {
        const int nW = *nW_ptr;
        const int mc = (nW < 2) ? nW : 2;
        const int w = b % nW;
        const bool use_l = (w < mc);
        const bool use_r = (w >= nW - mc);
        const int* ml = mask_l + (size_t)w * NTOK * MTOK;
        const int* mr = mask_r + (size_t)(2 - mc + (w - (nW - mc))) * NTOK * MTOK;
        const float scale = 0.125f;
        const float NEG = -3.402823466e38f;

        for (int qr = warp; qr < NTOK; qr += 8) {
            const int nm = (lane == 0) ? 5 : 4;
            float s[5];
            for (int j = 0; j < nm; j++) {
                const int m = lane + 32 * j;
                float a = Ss[qr * SSTR + m] * scale;
                float bias = (qr == 0)
                    ? ((m == 0) ? tb[191] : tb[192 + m - 1])
                    : ((m == 0) ? tb[320 + qr - 1] : tb[qr - m + 127]);
                a += bias;
                bool msk = false;
                if (use_l) msk = ml[qr * MTOK + m] != 0;
                if (use_r) msk = msk || (mr[qr * MTOK + m] != 0);
                s[j] = msk ? NEG : a;
            }
            float mx = s[0];
            for (int j = 1; j < nm; j++) mx = fmaxf(mx, s[j]);
            #pragma unroll
            for (int o = 16; o; o >>= 1) mx = fmaxf(mx, __shfl_xor_sync(~0u, mx, o));
            float sum = 0.f, p[5];
            for (int j = 0; j < nm; j++) { p[j] = __expf(s[j] - mx); sum += p[j]; }
            #pragma unroll
            for (int o = 16; o; o >>= 1) sum += __shfl_xor_sync(~0u, sum, o);
            const float inv = 1.f / sum;
            __syncwarp();
            // P written k-permuted so PV A-fragments pair as (2t, 2t+1)
            for (int j = 0; j < nm; j++) {
                const int m = lane + 32 * j;
                const int pm = (m & ~7) | ((m & 3) << 1) | ((m >> 2) & 1);
                Ss[qr * SSTR + pm] = p[j] * inv;
            }
            if (lane < 7) Ss[qr * SSTR + 129 + lane] = 0.f;   // NaN-safe pad
        }
    }
    asm volatile("cp.async.wait_group 0;" ::: "memory");
    __syncthreads();

    // ---- PV mma: warp owns d-cols warp*8..+7; V scalars from smem + cvt ----
    {
        const int wc = warp * 8 + g;
        float acc[5][4];
        #pragma unroll
        for (int i = 0; i < 5; i++)
            #pragma unroll
            for (int r = 0; r < 4; r++) acc[i][r] = 0.f;

        #pragma unroll
        for (int ks = 0; ks < 17; ks++) {
            const int mrow = ks * 8 + t;
            const unsigned b0 = f2tf32(Vs[mrow * VQS + wc]);
            const unsigned b1 = f2tf32(Vs[(mrow + 4) * VQS + wc]);
            const int k0 = ks * 8 + 2 * t;
            #pragma unroll
            for (int i = 0; i < 5; i++) {
                int r = i * 16 + g;
                uint2 lo = *(const uint2*)(Ss + r * SSTR + k0);
                uint2 hi = *(const uint2*)(Ss + (r + 8) * SSTR + k0);
                MMA_TF32(acc[i], lo.x, hi.x, lo.y, hi.y, b0, b1);
            }
        }
        // output raw fp32 (rounded in downstream GEMM), streaming store
        const int colbase = h * HDIM + warp * 8 + 2 * t;
        #pragma unroll
        for (int i = 0; i < 5; i++) {
            int q0 = i * 16 + g, q1 = q0 + 8;
            if (q0 < NTOK)
                st_cs2(ao + ((size_t)b * NTOK + q0) * CDIM + colbase,
                       acc[i][0], acc[i][1]);
            if (q1 < NTOK)
                st_cs2(ao + ((size_t)b * NTOK + q1) * CDIM + colbase,
                       acc[i][2], acc[i][3]);
        }
    }
}

// ---------------------------------------------------------------------------
extern "C" void kernel_launch(void* const* d_in, const int* in_sizes, int n_in,
                              void* d_out, int out_size)
{
    const float* x        = (const float*)d_in[0];
    const float* x_       = (const float*)d_in[1];
    const int*   mask_l   = (const int*)d_in[2];
    const int*   mask_r   = (const int*)d_in[3];
    const int*   nW_ptr   = (const int*)d_in[4];
    const float* Wq       = (const float*)d_in[5];
    const float* bq       = (const float*)d_in[6];
    const float* Wkv      = (const float*)d_in[7];
    const float* bkv      = (const float*)d_in[8];
    const float* Wp       = (const float*)d_in[9];
    const float* bp       = (const float*)d_in[10];
    const float* rel      = (const float*)d_in[11];
    const float* cls_self = (const float*)d_in[12];
    const float* cls_up   = (const float*)d_in[13];
    const float* cls_down = (const float*)d_in[14];

    const int BnW = in_sizes[0] / (NTOK * CDIM);   // 512
    const int Mq  = BnW * NTOK;                    // 33280
    const int Mkv = BnW * MTOK;                    // 66048

    float *qbuf, *kvbuf, *aobuf, *wqt, *wkvt, *wpt;
    cudaGetSymbolAddress((void**)&qbuf,  g_q);
    cudaGetSymbolAddress((void**)&kvbuf, g_kv);
    cudaGetSymbolAddress((void**)&aobuf, g_ao);
    cudaGetSymbolAddress((void**)&wqt,   g_wqt);
    cudaGetSymbolAddress((void**)&wkvt,  g_wkvt);
    cudaGetSymbolAddress((void**)&wpt,   g_wpt);

    transpose_tf32_perm<<<dim3(CDIM / 32, CDIM / 32), 256>>>(Wq, wqt, CDIM, CDIM);
    transpose_tf32_perm<<<dim3(2 * CDIM / 32, CDIM / 32), 256>>>(Wkv, wkvt, CDIM, 2 * CDIM);
    transpose_tf32_perm<<<dim3(CDIM / 32, CDIM / 32), 256>>>(Wp, wpt, CDIM, CDIM);

    const int gsm = 2 * STAGE_W * sizeof(float);   // 77824
    cudaFuncSetAttribute(gemm_raw, cudaFuncAttributeMaxDynamicSharedMemorySize, gsm);

    gemm_raw<<<dim3(CDIM / 128, Mq / 128), 256, gsm>>>(x, wqt, bq, qbuf, Mq, CDIM, CDIM);
    gemm_raw<<<dim3(2 * CDIM / 128, Mkv / 128), 256, gsm>>>(x_, wkvt, bkv, kvbuf, Mkv, 2 * CDIM, CDIM);

    const int asm_bytes = ATTN_W * sizeof(float);  // 101936
    cudaFuncSetAttribute(attn_tc, cudaFuncAttributeMaxDynamicSharedMemorySize, asm_bytes);
    attn_tc<<<dim3(NHEAD, BnW), 256, asm_bytes>>>(
        qbuf, kvbuf, mask_l, mask_r, nW_ptr, rel, cls_self, cls_up, cls_down, aobuf);

    gemm_raw<<<dim3(CDIM / 128, Mq / 128), 256, gsm>>>(aobuf, wpt, bp, (float*)d_out, Mq, CDIM, CDIM);
}